// round 3
// baseline (speedup 1.0000x reference)
#include <cuda_runtime.h>
#include <cfloat>

#define NN   50000
#define NE   800000
#define NEP  850000      // edges + self loops
#define HEADS 10
#define HID   10
#define CC    100        // HEADS*HID
#define NG    256
#define NOUT  10
#define NSLOPE 0.2f

// ---------------- scratch (static device globals; no allocations) -------------
__device__ float    g_A[NN * CC];        // h = X @ W (current layer features)
__device__ float    g_B[NN * CC];        // layer input / aggregation output
__device__ int      g_SRC[NEP];
__device__ int      g_DST[NEP];
__device__ int      g_BATCH[NN];
__device__ float    g_Ssrc[NN * HEADS];
__device__ float    g_Sdst[NN * HEADS];
__device__ unsigned g_Akey[NN * HEADS];  // encoded max keys
__device__ float    g_Den[NN * HEADS];
__device__ float    g_gsum[NG * CC];
__device__ float    g_cnt[NG];
__device__ int      g_is64;              // dtype flag for edge_index/batch

// monotonic float<->uint key (for atomicMax on floats, incl. negatives)
__device__ __forceinline__ unsigned fkey(float f) {
    unsigned u = __float_as_uint(f);
    return (u & 0x80000000u) ? ~u : (u | 0x80000000u);
}
__device__ __forceinline__ float funkey(unsigned k) {
    unsigned u = (k & 0x80000000u) ? (k ^ 0x80000000u) : ~k;
    return __uint_as_float(u);
}
#define AKEY_NEG_INF 0x00800000u   // == fkey(-FLT_MAX)

// ---------------- dtype detect + conversion -----------------------------------
__global__ void k_detect(const void* ei) {
    // int32 data read as int64 fuses two ids -> fails range check w.h.p.
    const long long* p = (const long long*)ei;
    int ok = 1;
    for (int i = 0; i < 16; i++) {
        long long v = p[i];
        if (v < 0 || v >= NN) ok = 0;
    }
    g_is64 = ok;
}
__global__ void k_convert_edges(const void* ei) {
    int e = blockIdx.x * blockDim.x + threadIdx.x;
    if (e >= NEP) return;
    int s, d;
    if (e < NE) {
        if (g_is64) {
            const long long* p = (const long long*)ei;
            s = (int)p[e]; d = (int)p[NE + e];
        } else {
            const int* p = (const int*)ei;
            s = p[e]; d = p[NE + e];
        }
    } else {
        s = d = e - NE;   // self loop
    }
    g_SRC[e] = s;
    g_DST[e] = d;
}
__global__ void k_convert_batch(const void* bp) {
    int n = blockIdx.x * blockDim.x + threadIdx.x;
    if (n >= NN) return;
    int b;
    if (g_is64) b = (int)((const long long*)bp)[n];
    else        b = ((const int*)bp)[n];
    g_BATCH[n] = b;
}

// ---------------- zero kernels ------------------------------------------------
__global__ void k_zero_layer() {
    int i = blockIdx.x * blockDim.x + threadIdx.x;
    int stride = gridDim.x * blockDim.x;
    for (int j = i; j < NN * HEADS; j += stride) { g_Akey[j] = AKEY_NEG_INF; g_Den[j] = 0.f; }
    for (int j = i; j < NN * CC; j += stride)   g_B[j] = 0.f;
}
__global__ void k_zero_pool() {
    int i = blockIdx.x * blockDim.x + threadIdx.x;
    int stride = gridDim.x * blockDim.x;
    for (int j = i; j < NG * CC; j += stride) g_gsum[j] = 0.f;
    for (int j = i; j < NG; j += stride)      g_cnt[j] = 0.f;
}

// ---------------- h = X @ W  (X:[N,Din], W:[Din,100]) -> g_A ------------------
__global__ __launch_bounds__(128) void k_gemm(const float* __restrict__ Xext,
                                              const float* __restrict__ W,
                                              int Din, int use_gb) {
    __shared__ float Wt[64 * CC];
    __shared__ float Xt[16][64];
    const float* X = use_gb ? (const float*)g_B : Xext;
    int n0 = blockIdx.x * 16;
    int c  = threadIdx.x;           // 0..127, cols 0..99 active
    float acc[16];
#pragma unroll
    for (int i = 0; i < 16; i++) acc[i] = 0.f;

    for (int k0 = 0; k0 < Din; k0 += 64) {
        int kk = min(64, Din - k0);
        for (int idx = threadIdx.x; idx < kk * CC; idx += blockDim.x)
            Wt[idx] = W[(size_t)(k0 + idx / CC) * CC + (idx % CC)];
        for (int idx = threadIdx.x; idx < 16 * kk; idx += blockDim.x) {
            int nn = idx / kk, kq = idx - nn * kk;
            int n = n0 + nn;
            Xt[nn][kq] = (n < NN) ? X[(size_t)n * Din + k0 + kq] : 0.f;
        }
        __syncthreads();
        if (c < CC) {
#pragma unroll 1
            for (int nn = 0; nn < 16; nn++) {
                float a = 0.f;
#pragma unroll 4
                for (int k = 0; k < kk; k++) a += Xt[nn][k] * Wt[k * CC + c];
                acc[nn] += a;
            }
        }
        __syncthreads();
    }
    if (c < CC) {
#pragma unroll
        for (int nn = 0; nn < 16; nn++) {
            int n = n0 + nn;
            if (n < NN) g_A[(size_t)n * CC + c] = acc[nn];
        }
    }
}

// ---------------- per-node attention scores -----------------------------------
__global__ void k_scores(const float* __restrict__ asrc, const float* __restrict__ adst) {
    int idx = blockIdx.x * blockDim.x + threadIdx.x;
    if (idx >= NN * HEADS) return;
    int n = idx / HEADS, h = idx - n * HEADS;
    float s1 = 0.f, s2 = 0.f;
#pragma unroll
    for (int f = 0; f < HID; f++) {
        float v = g_A[n * CC + h * HID + f];
        s1 += v * asrc[h * HID + f];
        s2 += v * adst[h * HID + f];
    }
    g_Ssrc[idx] = s1;
    g_Sdst[idx] = s2;
}

// ---------------- edge pass 1: segment max ------------------------------------
__global__ void k_edge_max() {
    int idx = blockIdx.x * blockDim.x + threadIdx.x;
    if (idx >= NEP * HEADS) return;
    int e = idx / HEADS, h = idx - e * HEADS;
    int s = g_SRC[e], d = g_DST[e];
    float al = g_Ssrc[s * HEADS + h] + g_Sdst[d * HEADS + h];
    al = (al >= 0.f) ? al : NSLOPE * al;
    atomicMax(&g_Akey[d * HEADS + h], fkey(al));
}

// ---------------- edge pass 2: exp + segment sum ------------------------------
__global__ void k_edge_exp() {
    int idx = blockIdx.x * blockDim.x + threadIdx.x;
    if (idx >= NEP * HEADS) return;
    int e = idx / HEADS, h = idx - e * HEADS;
    int s = g_SRC[e], d = g_DST[e];
    float al = g_Ssrc[s * HEADS + h] + g_Sdst[d * HEADS + h];
    al = (al >= 0.f) ? al : NSLOPE * al;
    float m  = funkey(g_Akey[d * HEADS + h]);
    atomicAdd(&g_Den[d * HEADS + h], __expf(al - m));
}

// ---------------- edge pass 3: weighted aggregation into g_B ------------------
// thread per (edge, head): recompute coef, 10 feature loads + 10 atomicAdds
__global__ void k_agg() {
    int idx = blockIdx.x * blockDim.x + threadIdx.x;
    if (idx >= NEP * HEADS) return;
    int e = idx / HEADS, h = idx - e * HEADS;
    int s = g_SRC[e], d = g_DST[e];
    float al = g_Ssrc[s * HEADS + h] + g_Sdst[d * HEADS + h];
    al = (al >= 0.f) ? al : NSLOPE * al;
    float m   = funkey(g_Akey[d * HEADS + h]);
    float den = g_Den[d * HEADS + h];
    float coef = __expf(al - m) / den;
    const float* hp = &g_A[(size_t)s * CC + h * HID];
    float* op = &g_B[(size_t)d * CC + h * HID];
#pragma unroll
    for (int f = 0; f < HID; f++)
        atomicAdd(op + f, hp[f] * coef);
}

// ---------------- bias + relu (in place on g_B) -------------------------------
__global__ void k_bias_relu(const float* __restrict__ b) {
    int idx = blockIdx.x * blockDim.x + threadIdx.x;
    if (idx >= NN * CC) return;
    int c = idx % CC;
    float v = g_B[idx] + b[c];
    g_B[idx] = (v > 0.f) ? v : 0.f;
}

// ---------------- pooling -----------------------------------------------------
__global__ void k_count() {
    int n = blockIdx.x * blockDim.x + threadIdx.x;
    if (n >= NN) return;
    atomicAdd(&g_cnt[g_BATCH[n]], 1.f);
}
__global__ __launch_bounds__(128) void k_pool() {
    int c = threadIdx.x;
    if (c >= CC) return;
    int n0 = blockIdx.x * 256;
    if (n0 >= NN) return;
    int nend = min(n0 + 256, NN);
    int cur = g_BATCH[n0];
    float acc = 0.f;
    for (int n = n0; n < nend; n++) {
        int g = g_BATCH[n];
        if (g != cur) { atomicAdd(&g_gsum[cur * CC + c], acc); acc = 0.f; cur = g; }
        acc += g_B[(size_t)n * CC + c];
    }
    atomicAdd(&g_gsum[cur * CC + c], acc);
}

// ---------------- final FC ----------------------------------------------------
__global__ void k_fc(const float* __restrict__ Wfc, const float* __restrict__ bfc,
                     float* __restrict__ out) {
    int idx = blockIdx.x * blockDim.x + threadIdx.x;
    if (idx >= NG * NOUT) return;
    int g = idx / NOUT, o = idx - g * NOUT;
    float inv = 1.f / fmaxf(g_cnt[g], 1.f);
    float s = 0.f;
#pragma unroll 4
    for (int c = 0; c < CC; c++) s += g_gsum[g * CC + c] * Wfc[c * NOUT + o];
    out[idx] = s * inv + bfc[o];
}

// ---------------- driver ------------------------------------------------------
extern "C" void kernel_launch(void* const* d_in, const int* in_sizes, int n_in,
                              void* d_out, int out_size) {
    const float* x     = (const float*)d_in[0];
    const void*  ei    = d_in[1];
    const void*  batch = d_in[2];
    const float* W[3]    = { (const float*)d_in[3],  (const float*)d_in[7],  (const float*)d_in[11] };
    const float* asrc[3] = { (const float*)d_in[4],  (const float*)d_in[8],  (const float*)d_in[12] };
    const float* adst[3] = { (const float*)d_in[5],  (const float*)d_in[9],  (const float*)d_in[13] };
    const float* bb[3]   = { (const float*)d_in[6],  (const float*)d_in[10], (const float*)d_in[14] };
    const float* Wfc = (const float*)d_in[15];
    const float* bfc = (const float*)d_in[16];
    float* out = (float*)d_out;

    const int TB = 256;
    int gNH = (NN * HEADS + TB - 1) / TB;
    int gEH = (NEP * HEADS + TB - 1) / TB;
    int gNC = (NN * CC + TB - 1) / TB;

    k_detect<<<1, 1>>>(ei);
    k_convert_edges<<<(NEP + TB - 1) / TB, TB>>>(ei);
    k_convert_batch<<<(NN + TB - 1) / TB, TB>>>(batch);

    for (int l = 0; l < 3; l++) {
        int Din = (l == 0) ? 128 : CC;
        k_gemm<<<(NN + 15) / 16, 128>>>(x, W[l], Din, l > 0 ? 1 : 0);
        k_zero_layer<<<2048, TB>>>();
        k_scores<<<gNH, TB>>>(asrc[l], adst[l]);
        k_edge_max<<<gEH, TB>>>();
        k_edge_exp<<<gEH, TB>>>();
        k_agg<<<gEH, TB>>>();
        k_bias_relu<<<gNC, TB>>>(bb[l]);
    }

    k_zero_pool<<<128, TB>>>();
    k_count<<<(NN + TB - 1) / TB, TB>>>();
    k_pool<<<(NN + 255) / 256, 128>>>();
    k_fc<<<(NG * NOUT + TB - 1) / TB, TB>>>(Wfc, bfc, out);
}

// round 4
// speedup vs baseline: 2.4251x; 2.4251x over previous
#include <cuda_runtime.h>
#include <cfloat>

#define NN   50000
#define NE   800000
#define NEP  850000      // edges + self loops
#define HEADS 10
#define HID   10
#define CC    100        // HEADS*HID
#define NG    256
#define NOUT  10
#define NSLOPE 0.2f
#define GR   32          // gemm rows per block

// ---------------- scratch (static device globals; no allocations) -------------
__device__ float    g_A[NN * CC];        // h = X @ W (current layer features)
__device__ float    g_B[NN * CC];        // layer input / aggregation output
__device__ float    g_EX[NEP * HEADS];   // exp -> normalized coef
__device__ int      g_SRC[NEP];
__device__ int      g_DST[NEP];
__device__ int      g_BATCH[NN];
__device__ float    g_Ssrc[NN * HEADS];
__device__ float    g_Sdst[NN * HEADS];
__device__ unsigned g_Akey[NN * HEADS];  // encoded max keys
__device__ float    g_Den[NN * HEADS];
__device__ float    g_gsum[NG * CC];
__device__ float    g_cnt[NG];
__device__ int      g_is64;              // dtype flag for edge_index/batch

// monotonic float<->uint key (for atomicMax on floats, incl. negatives)
__device__ __forceinline__ unsigned fkey(float f) {
    unsigned u = __float_as_uint(f);
    return (u & 0x80000000u) ? ~u : (u | 0x80000000u);
}
__device__ __forceinline__ float funkey(unsigned k) {
    unsigned u = (k & 0x80000000u) ? (k ^ 0x80000000u) : ~k;
    return __uint_as_float(u);
}
#define AKEY_NEG_INF 0x00800000u   // == fkey(-FLT_MAX)

// ---------------- dtype detect + conversion -----------------------------------
__global__ void k_detect(const void* ei) {
    const long long* p = (const long long*)ei;
    int ok = 1;
    for (int i = 0; i < 16; i++) {
        long long v = p[i];
        if (v < 0 || v >= NN) ok = 0;
    }
    g_is64 = ok;
}
__global__ void k_convert_edges(const void* ei) {
    int e = blockIdx.x * blockDim.x + threadIdx.x;
    if (e >= NEP) return;
    int s, d;
    if (e < NE) {
        if (g_is64) {
            const long long* p = (const long long*)ei;
            s = (int)p[e]; d = (int)p[NE + e];
        } else {
            const int* p = (const int*)ei;
            s = p[e]; d = p[NE + e];
        }
    } else {
        s = d = e - NE;   // self loop
    }
    g_SRC[e] = s;
    g_DST[e] = d;
}
__global__ void k_convert_batch(const void* bp) {
    int n = blockIdx.x * blockDim.x + threadIdx.x;
    if (n >= NN) return;
    int b;
    if (g_is64) b = (int)((const long long*)bp)[n];
    else        b = ((const int*)bp)[n];
    g_BATCH[n] = b;
}

// ---------------- zero kernels ------------------------------------------------
__global__ void k_zero_layer() {
    int i = blockIdx.x * blockDim.x + threadIdx.x;
    int stride = gridDim.x * blockDim.x;
    for (int j = i; j < NN * HEADS; j += stride) { g_Akey[j] = AKEY_NEG_INF; g_Den[j] = 0.f; }
    float4 z = {0.f, 0.f, 0.f, 0.f};
    for (int j = i; j < NN * CC / 4; j += stride) ((float4*)g_B)[j] = z;
}
__global__ void k_zero_pool() {
    int i = blockIdx.x * blockDim.x + threadIdx.x;
    int stride = gridDim.x * blockDim.x;
    for (int j = i; j < NG * CC; j += stride) g_gsum[j] = 0.f;
    for (int j = i; j < NG; j += stride)      g_cnt[j] = 0.f;
}

// ---------------- h = X @ W  (X:[N,Din], W:[Din,100]) -> g_A ------------------
// 128 threads: c = tid (100 active cols). Block computes GR=32 rows.
// Xs staged TRANSPOSED: Xs[k][r], broadcast reads, vectorizable over r.
__global__ __launch_bounds__(128) void k_gemm(const float* __restrict__ Xext,
                                              const float* __restrict__ W,
                                              int Din, int use_gb) {
    __shared__ float Wt[64 * CC];        // 25.6 KB
    __shared__ float Xs[64][GR + 4];     // 9.2 KB, padded (36 % 4 == 0, 16B aligned rows)
    const float* X = use_gb ? (const float*)g_B : Xext;
    int n0 = blockIdx.x * GR;
    int c  = threadIdx.x;
    float acc[GR];
#pragma unroll
    for (int r = 0; r < GR; r++) acc[r] = 0.f;

    for (int k0 = 0; k0 < Din; k0 += 64) {
        int kk = min(64, Din - k0);
        for (int idx = threadIdx.x; idx < kk * CC; idx += 128)
            Wt[idx] = W[(size_t)(k0 + idx / CC) * CC + (idx % CC)];
        for (int idx = threadIdx.x; idx < GR * kk; idx += 128) {
            int r = idx / kk, k = idx - r * kk;
            int n = n0 + r;
            Xs[k][r] = (n < NN) ? X[(size_t)n * Din + k0 + k] : 0.f;
        }
        __syncthreads();
        if (c < CC) {
            for (int k = 0; k < kk; k++) {
                float w = Wt[k * CC + c];
#pragma unroll
                for (int rq = 0; rq < GR / 4; rq++) {
                    float4 xv = *(const float4*)&Xs[k][rq * 4];
                    acc[rq * 4 + 0] += xv.x * w;
                    acc[rq * 4 + 1] += xv.y * w;
                    acc[rq * 4 + 2] += xv.z * w;
                    acc[rq * 4 + 3] += xv.w * w;
                }
            }
        }
        __syncthreads();
    }
    if (c < CC) {
#pragma unroll
        for (int r = 0; r < GR; r++) {
            int n = n0 + r;
            if (n < NN) g_A[(size_t)n * CC + c] = acc[r];
        }
    }
}

// ---------------- per-node attention scores -----------------------------------
__global__ void k_scores(const float* __restrict__ asrc, const float* __restrict__ adst) {
    int idx = blockIdx.x * blockDim.x + threadIdx.x;
    if (idx >= NN * HEADS) return;
    int n = idx / HEADS, h = idx - n * HEADS;
    float s1 = 0.f, s2 = 0.f;
#pragma unroll
    for (int f = 0; f < HID; f++) {
        float v = g_A[n * CC + h * HID + f];
        s1 += v * asrc[h * HID + f];
        s2 += v * adst[h * HID + f];
    }
    g_Ssrc[idx] = s1;
    g_Sdst[idx] = s2;
}

// ---------------- edge pass 1: segment max ------------------------------------
__global__ void k_edge_max() {
    int idx = blockIdx.x * blockDim.x + threadIdx.x;
    if (idx >= NEP * HEADS) return;
    int e = idx / HEADS, h = idx - e * HEADS;
    int s = g_SRC[e], d = g_DST[e];
    float al = g_Ssrc[s * HEADS + h] + g_Sdst[d * HEADS + h];
    al = (al >= 0.f) ? al : NSLOPE * al;
    atomicMax(&g_Akey[d * HEADS + h], fkey(al));
}

// ---------------- edge pass 2: exp + segment sum (store raw exp) --------------
__global__ void k_edge_exp() {
    int idx = blockIdx.x * blockDim.x + threadIdx.x;
    if (idx >= NEP * HEADS) return;
    int e = idx / HEADS, h = idx - e * HEADS;
    int s = g_SRC[e], d = g_DST[e];
    float al = g_Ssrc[s * HEADS + h] + g_Sdst[d * HEADS + h];
    al = (al >= 0.f) ? al : NSLOPE * al;
    float m  = funkey(g_Akey[d * HEADS + h]);
    float ex = __expf(al - m);
    g_EX[idx] = ex;
    atomicAdd(&g_Den[d * HEADS + h], ex);
}

// ---------------- edge pass 3: normalize coef ---------------------------------
__global__ void k_coef() {
    int idx = blockIdx.x * blockDim.x + threadIdx.x;
    if (idx >= NEP * HEADS) return;
    int e = idx / HEADS, h = idx - e * HEADS;
    int d = g_DST[e];
    g_EX[idx] = g_EX[idx] / g_Den[d * HEADS + h];
}

// ---------------- edge pass 4: weighted aggregation (vector RED) --------------
// thread per (edge, quad of 4 cols): LDG.128 + RED.128
__global__ void k_agg() {
    int idx = blockIdx.x * blockDim.x + threadIdx.x;
    if (idx >= NEP * 25) return;
    int e = idx / 25, q = idx - e * 25;
    int s = g_SRC[e], d = g_DST[e];
    int c0 = q * 4;
    int h0 = c0 / HID;
    int h3 = (c0 + 3) / HID;
    float cfa = g_EX[e * HEADS + h0];
    float cfb = (h3 == h0) ? cfa : g_EX[e * HEADS + h3];
    float cf1 = ((c0 + 1) / HID == h0) ? cfa : cfb;
    float cf2 = ((c0 + 2) / HID == h0) ? cfa : cfb;
    const float4 hv = *(const float4*)&g_A[(size_t)s * CC + c0];
    float mx = hv.x * cfa, my = hv.y * cf1, mz = hv.z * cf2, mw = hv.w * cfb;
    float* p = &g_B[(size_t)d * CC + c0];
    asm volatile("red.global.add.v4.f32 [%0], {%1,%2,%3,%4};"
                 :: "l"(p), "f"(mx), "f"(my), "f"(mz), "f"(mw)
                 : "memory");
}

// ---------------- bias + relu (in place on g_B) -------------------------------
__global__ void k_bias_relu(const float* __restrict__ b) {
    int idx = blockIdx.x * blockDim.x + threadIdx.x;
    if (idx >= NN * CC) return;
    int c = idx % CC;
    float v = g_B[idx] + b[c];
    g_B[idx] = (v > 0.f) ? v : 0.f;
}

// ---------------- pooling -----------------------------------------------------
__global__ void k_count() {
    int n = blockIdx.x * blockDim.x + threadIdx.x;
    if (n >= NN) return;
    atomicAdd(&g_cnt[g_BATCH[n]], 1.f);
}
__global__ __launch_bounds__(128) void k_pool() {
    int c = threadIdx.x;
    if (c >= CC) return;
    int n0 = blockIdx.x * 256;
    if (n0 >= NN) return;
    int nend = min(n0 + 256, NN);
    int cur = g_BATCH[n0];
    float acc = 0.f;
    for (int n = n0; n < nend; n++) {
        int g = g_BATCH[n];
        if (g != cur) { atomicAdd(&g_gsum[cur * CC + c], acc); acc = 0.f; cur = g; }
        acc += g_B[(size_t)n * CC + c];
    }
    atomicAdd(&g_gsum[cur * CC + c], acc);
}

// ---------------- final FC ----------------------------------------------------
__global__ void k_fc(const float* __restrict__ Wfc, const float* __restrict__ bfc,
                     float* __restrict__ out) {
    int idx = blockIdx.x * blockDim.x + threadIdx.x;
    if (idx >= NG * NOUT) return;
    int g = idx / NOUT, o = idx - g * NOUT;
    float inv = 1.f / fmaxf(g_cnt[g], 1.f);
    float s = 0.f;
#pragma unroll 4
    for (int c = 0; c < CC; c++) s += g_gsum[g * CC + c] * Wfc[c * NOUT + o];
    out[idx] = s * inv + bfc[o];
}

// ---------------- driver ------------------------------------------------------
extern "C" void kernel_launch(void* const* d_in, const int* in_sizes, int n_in,
                              void* d_out, int out_size) {
    const float* x     = (const float*)d_in[0];
    const void*  ei    = d_in[1];
    const void*  batch = d_in[2];
    const float* W[3]    = { (const float*)d_in[3],  (const float*)d_in[7],  (const float*)d_in[11] };
    const float* asrc[3] = { (const float*)d_in[4],  (const float*)d_in[8],  (const float*)d_in[12] };
    const float* adst[3] = { (const float*)d_in[5],  (const float*)d_in[9],  (const float*)d_in[13] };
    const float* bb[3]   = { (const float*)d_in[6],  (const float*)d_in[10], (const float*)d_in[14] };
    const float* Wfc = (const float*)d_in[15];
    const float* bfc = (const float*)d_in[16];
    float* out = (float*)d_out;

    const int TB = 256;
    int gNH = (NN * HEADS + TB - 1) / TB;
    int gEH = (NEP * HEADS + TB - 1) / TB;
    int gEQ = (NEP * 25 + TB - 1) / TB;
    int gNC = (NN * CC + TB - 1) / TB;

    k_detect<<<1, 1>>>(ei);
    k_convert_edges<<<(NEP + TB - 1) / TB, TB>>>(ei);
    k_convert_batch<<<(NN + TB - 1) / TB, TB>>>(batch);

    for (int l = 0; l < 3; l++) {
        int Din = (l == 0) ? 128 : CC;
        k_gemm<<<(NN + GR - 1) / GR, 128>>>(x, W[l], Din, l > 0 ? 1 : 0);
        k_zero_layer<<<2048, TB>>>();
        k_scores<<<gNH, TB>>>(asrc[l], adst[l]);
        k_edge_max<<<gEH, TB>>>();
        k_edge_exp<<<gEH, TB>>>();
        k_coef<<<gEH, TB>>>();
        k_agg<<<gEQ, TB>>>();
        k_bias_relu<<<gNC, TB>>>(bb[l]);
    }

    k_zero_pool<<<128, TB>>>();
    k_count<<<(NN + TB - 1) / TB, TB>>>();
    k_pool<<<(NN + 255) / 256, 128>>>();
    k_fc<<<(NG * NOUT + TB - 1) / TB, TB>>>(Wfc, bfc, out);
}

// round 6
// speedup vs baseline: 2.9430x; 1.2136x over previous
#include <cuda_runtime.h>
#include <cfloat>

#define NN   50000
#define NE   800000
#define NEP  850000      // edges + self loops
#define HEADS 10
#define HID   10
#define CC    100        // HEADS*HID
#define NG    256
#define NOUT  10
#define NSLOPE 0.2f
#define GR   32          // gemm rows per block

// ---------------- scratch (static device globals; no allocations) -------------
__device__ float g_A[NN * CC];        // h = X @ W (current layer features)
__device__ float g_B[NN * CC];        // layer input / aggregation output
__device__ float g_EXC[NEP * HEADS];  // alpha -> normalized coef (CSR order)
__device__ int   g_SRC[NEP];
__device__ int   g_DST[NEP];
__device__ int   g_CSRC[NEP];         // CSR: src per position (sorted by dst)
__device__ int   g_CNT[NN];
__device__ int   g_ROW[NN + 1];
__device__ int   g_WOFF[NN];
__device__ int   g_BATCH[NN];
__device__ float g_Ssrc[NN * HEADS];
__device__ float g_Sdst[NN * HEADS];
__device__ float g_gsum[NG * CC];
__device__ float g_cnt[NG];
__device__ int   g_is64;

// ---------------- dtype detect + conversion -----------------------------------
__global__ void k_detect(const void* ei) {
    const long long* p = (const long long*)ei;
    int ok = 1;
    for (int i = 0; i < 16; i++) {
        long long v = p[i];
        if (v < 0 || v >= NN) ok = 0;
    }
    g_is64 = ok;
}
__global__ void k_convert_edges(const void* ei) {
    int e = blockIdx.x * blockDim.x + threadIdx.x;
    if (e >= NEP) return;
    int s, d;
    if (e < NE) {
        if (g_is64) {
            const long long* p = (const long long*)ei;
            s = (int)p[e]; d = (int)p[NE + e];
        } else {
            const int* p = (const int*)ei;
            s = p[e]; d = p[NE + e];
        }
    } else {
        s = d = e - NE;   // self loop
    }
    g_SRC[e] = s;
    g_DST[e] = d;
}
__global__ void k_convert_batch(const void* bp) {
    int n = blockIdx.x * blockDim.x + threadIdx.x;
    if (n >= NN) return;
    g_BATCH[n] = g_is64 ? (int)((const long long*)bp)[n] : ((const int*)bp)[n];
}

// ---------------- CSR build ---------------------------------------------------
__global__ void k_zero_cnt() {
    int n = blockIdx.x * blockDim.x + threadIdx.x;
    if (n < NN) g_CNT[n] = 0;
}
__global__ void k_deg() {
    int e = blockIdx.x * blockDim.x + threadIdx.x;
    if (e >= NEP) return;
    atomicAdd(&g_CNT[g_DST[e]], 1);
}
__global__ __launch_bounds__(1024) void k_scan() {
    __shared__ int wsum[32];
    __shared__ int s_carry;
    int tid = threadIdx.x;
    int lane = tid & 31, warp = tid >> 5;
    if (tid == 0) s_carry = 0;
    __syncthreads();
    for (int base = 0; base < NN; base += 1024) {
        int v = (base + tid < NN) ? g_CNT[base + tid] : 0;
        int x = v;
#pragma unroll
        for (int o = 1; o < 32; o <<= 1) {
            int y = __shfl_up_sync(~0u, x, o);
            if (lane >= o) x += y;
        }
        if (lane == 31) wsum[warp] = x;
        __syncthreads();
        if (warp == 0) {
            int w = wsum[lane];
#pragma unroll
            for (int o = 1; o < 32; o <<= 1) {
                int y = __shfl_up_sync(~0u, w, o);
                if (lane >= o) w += y;
            }
            wsum[lane] = w;
        }
        __syncthreads();
        int warpoff = (warp == 0) ? 0 : wsum[warp - 1];
        int ex = s_carry + warpoff + x - v;
        if (base + tid < NN) { g_ROW[base + tid] = ex; g_WOFF[base + tid] = ex; }
        __syncthreads();
        if (tid == 1023) s_carry += warpoff + x;   // running total
        __syncthreads();
    }
    if (tid == 0) g_ROW[NN] = s_carry;
}
__global__ void k_scatter() {
    int e = blockIdx.x * blockDim.x + threadIdx.x;
    if (e >= NEP) return;
    int d = g_DST[e];
    int pos = atomicAdd(&g_WOFF[d], 1);
    g_CSRC[pos] = g_SRC[e];
}

// ---------------- h = X @ W -> g_A  (8x4 register tile) -----------------------
// 128 threads: ct = tid%32 -> cols ct*4..+3 (of 128 padded), rt = tid/32 -> 8 rows
__global__ __launch_bounds__(128) void k_gemm(const float* __restrict__ Xext,
                                              const float* __restrict__ W,
                                              int Din, int use_gb) {
    __shared__ float Wt[64 * 128];       // 32 KB, cols padded to 128
    __shared__ float Xs[64][GR + 4];     // 9.2 KB (stride 36 floats = 144B, 16B-aligned)
    const float* X = use_gb ? (const float*)g_B : Xext;
    int n0 = blockIdx.x * GR;
    int ct = threadIdx.x & 31;
    int rt = threadIdx.x >> 5;
    float acc[8][4];
#pragma unroll
    for (int i = 0; i < 8; i++)
#pragma unroll
        for (int j = 0; j < 4; j++) acc[i][j] = 0.f;

    for (int k0 = 0; k0 < Din; k0 += 64) {
        int kk = min(64, Din - k0);
        for (int idx = threadIdx.x; idx < kk * 128; idx += 128) {
            int k = idx >> 7, c = idx & 127;
            Wt[idx] = (c < CC) ? W[(size_t)(k0 + k) * CC + c] : 0.f;
        }
        for (int idx = threadIdx.x; idx < GR * kk; idx += 128) {
            int r = idx / kk, k = idx - r * kk;
            int n = n0 + r;
            Xs[k][r] = (n < NN) ? X[(size_t)n * Din + k0 + k] : 0.f;
        }
        __syncthreads();
        for (int k = 0; k < kk; k++) {
            float4 w  = *(const float4*)&Wt[k * 128 + ct * 4];
            float4 xa = *(const float4*)&Xs[k][rt * 8];
            float4 xb = *(const float4*)&Xs[k][rt * 8 + 4];
            float xr[8] = {xa.x, xa.y, xa.z, xa.w, xb.x, xb.y, xb.z, xb.w};
            float wr[4] = {w.x, w.y, w.z, w.w};
#pragma unroll
            for (int i = 0; i < 8; i++)
#pragma unroll
                for (int j = 0; j < 4; j++) acc[i][j] += xr[i] * wr[j];
        }
        __syncthreads();
    }
    if (ct < 25) {   // cols ct*4..ct*4+3 all < 100
#pragma unroll
        for (int i = 0; i < 8; i++) {
            int n = n0 + rt * 8 + i;
            if (n < NN) {
                float4 v = make_float4(acc[i][0], acc[i][1], acc[i][2], acc[i][3]);
                *(float4*)&g_A[(size_t)n * CC + ct * 4] = v;
            }
        }
    }
}

// ---------------- per-node attention scores -----------------------------------
__global__ void k_scores(const float* __restrict__ asrc, const float* __restrict__ adst) {
    int idx = blockIdx.x * blockDim.x + threadIdx.x;
    if (idx >= NN * HEADS) return;
    int n = idx / HEADS, h = idx - n * HEADS;
    float s1 = 0.f, s2 = 0.f;
#pragma unroll
    for (int f = 0; f < HID; f++) {
        float v = g_A[n * CC + h * HID + f];
        s1 += v * asrc[h * HID + f];
        s2 += v * adst[h * HID + f];
    }
    g_Ssrc[idx] = s1;
    g_Sdst[idx] = s2;
}

// ---------------- softmax per (dst, head): online max/sum, no atomics ---------
__global__ void k_softmax() {
    int idx = blockIdx.x * blockDim.x + threadIdx.x;
    if (idx >= NN * HEADS) return;
    int d = idx / HEADS, h = idx - d * HEADS;
    int row0 = g_ROW[d], row1 = g_ROW[d + 1];
    float sd = g_Sdst[idx];
    float m = -FLT_MAX, den = 0.f;
    for (int i = row0; i < row1; i++) {
        int s = g_CSRC[i];
        float a = g_Ssrc[s * HEADS + h] + sd;
        a = (a >= 0.f) ? a : NSLOPE * a;
        g_EXC[i * HEADS + h] = a;            // stash alpha
        if (a > m) { den = den * __expf(m - a) + 1.f; m = a; }
        else       { den += __expf(a - m); }
    }
    float inv = 1.f / den;
    for (int i = row0; i < row1; i++) {
        float a = g_EXC[i * HEADS + h];
        g_EXC[i * HEADS + h] = __expf(a - m) * inv;
    }
}

// ---------------- aggregation: block-per-dst coalesced gather + bias + relu ---
__global__ __launch_bounds__(128) void k_agg(const float* __restrict__ bias) {
    int d = blockIdx.x;
    int c = threadIdx.x;
    int row0 = g_ROW[d], row1 = g_ROW[d + 1];
    int hh = c / HID;                    // head for this column
    if (c < CC) {
        float acc = 0.f;
        for (int i = row0; i < row1; i++) {
            int s = g_CSRC[i];
            float coef = g_EXC[i * HEADS + hh];
            acc += coef * g_A[(size_t)s * CC + c];
        }
        float v = acc + bias[c];
        g_B[(size_t)d * CC + c] = (v > 0.f) ? v : 0.f;
    }
}

// ---------------- pooling -----------------------------------------------------
__global__ void k_zero_pool() {
    int i = blockIdx.x * blockDim.x + threadIdx.x;
    int stride = gridDim.x * blockDim.x;
    for (int j = i; j < NG * CC; j += stride) g_gsum[j] = 0.f;
    for (int j = i; j < NG; j += stride)      g_cnt[j] = 0.f;
}
__global__ void k_count() {
    int n = blockIdx.x * blockDim.x + threadIdx.x;
    if (n >= NN) return;
    atomicAdd(&g_cnt[g_BATCH[n]], 1.f);
}
__global__ __launch_bounds__(128) void k_pool() {
    int c = threadIdx.x;
    if (c >= CC) return;
    int n0 = blockIdx.x * 256;
    if (n0 >= NN) return;
    int nend = min(n0 + 256, NN);
    int cur = g_BATCH[n0];
    float acc = 0.f;
    for (int n = n0; n < nend; n++) {
        int g = g_BATCH[n];
        if (g != cur) { atomicAdd(&g_gsum[cur * CC + c], acc); acc = 0.f; cur = g; }
        acc += g_B[(size_t)n * CC + c];
    }
    atomicAdd(&g_gsum[cur * CC + c], acc);
}

// ---------------- final FC ----------------------------------------------------
__global__ void k_fc(const float* __restrict__ Wfc, const float* __restrict__ bfc,
                     float* __restrict__ out) {
    int idx = blockIdx.x * blockDim.x + threadIdx.x;
    if (idx >= NG * NOUT) return;
    int g = idx / NOUT, o = idx - g * NOUT;
    float inv = 1.f / fmaxf(g_cnt[g], 1.f);
    float s = 0.f;
#pragma unroll 4
    for (int c = 0; c < CC; c++) s += g_gsum[g * CC + c] * Wfc[c * NOUT + o];
    out[idx] = s * inv + bfc[o];
}

// ---------------- driver ------------------------------------------------------
extern "C" void kernel_launch(void* const* d_in, const int* in_sizes, int n_in,
                              void* d_out, int out_size) {
    const float* x     = (const float*)d_in[0];
    const void*  ei    = d_in[1];
    const void*  batch = d_in[2];
    const float* W[3]    = { (const float*)d_in[3],  (const float*)d_in[7],  (const float*)d_in[11] };
    const float* asrc[3] = { (const float*)d_in[4],  (const float*)d_in[8],  (const float*)d_in[12] };
    const float* adst[3] = { (const float*)d_in[5],  (const float*)d_in[9],  (const float*)d_in[13] };
    const float* bb[3]   = { (const float*)d_in[6],  (const float*)d_in[10], (const float*)d_in[14] };
    const float* Wfc = (const float*)d_in[15];
    const float* bfc = (const float*)d_in[16];
    float* out = (float*)d_out;

    const int TB = 256;
    int gNH = (NN * HEADS + TB - 1) / TB;
    int gE  = (NEP + TB - 1) / TB;
    int gN  = (NN + TB - 1) / TB;

    // one-time per call: dtype, edge lists, CSR
    k_detect<<<1, 1>>>(ei);
    k_convert_edges<<<gE, TB>>>(ei);
    k_convert_batch<<<gN, TB>>>(batch);
    k_zero_cnt<<<gN, TB>>>();
    k_deg<<<gE, TB>>>();
    k_scan<<<1, 1024>>>();
    k_scatter<<<gE, TB>>>();

    for (int l = 0; l < 3; l++) {
        int Din = (l == 0) ? 128 : CC;
        k_gemm<<<(NN + GR - 1) / GR, 128>>>(x, W[l], Din, l > 0 ? 1 : 0);
        k_scores<<<gNH, TB>>>(asrc[l], adst[l]);
        k_softmax<<<gNH, TB>>>();
        k_agg<<<NN, 128>>>(bb[l]);
    }

    k_zero_pool<<<128, TB>>>();
    k_count<<<gN, TB>>>();
    k_pool<<<(NN + 255) / 256, 128>>>();
    k_fc<<<(NG * NOUT + TB - 1) / TB, TB>>>(Wfc, bfc, out);
}

// round 7
// speedup vs baseline: 3.1344x; 1.0650x over previous
#include <cuda_runtime.h>
#include <cuda_fp16.h>
#include <cfloat>

#define NN   50000
#define NE   800000
#define NEP  850000      // edges + self loops
#define HEADS 10
#define HID   10
#define CC    100        // HEADS*HID
#define NG    256
#define NOUT  10
#define NSLOPE 0.2f
#define GR   32          // gemm rows per block

// ---------------- scratch (static device globals; no allocations) -------------
__device__ float  g_A[NN * CC];        // h = X @ W (fp32, for scores)
__device__ __half g_Ah[NN * CC];       // h in fp16 (for aggregation gather)
__device__ float  g_B[NN * CC];        // layer input / aggregation output
__device__ float  g_EXC[NEP * HEADS];  // exp(alpha) in CSR order
__device__ int    g_SRC[NEP];
__device__ int    g_DST[NEP];
__device__ int    g_CSRC[NEP];         // CSR: src per position (sorted by dst)
__device__ int    g_CNT[NN];
__device__ int    g_ROW[NN + 1];
__device__ int    g_WOFF[NN];
__device__ int    g_BATCH[NN];
__device__ float  g_Ssrc[NN * HEADS];
__device__ float  g_Sdst[NN * HEADS];
__device__ float  g_IDen[NN * HEADS];  // 1/sum(exp)
__device__ float  g_gsum[NG * CC];
__device__ float  g_cnt[NG];
__device__ int    g_is64;

// ---------------- dtype detect ------------------------------------------------
__global__ void k_detect(const void* ei) {
    const long long* p = (const long long*)ei;
    int ok = 1;
    for (int i = 0; i < 16; i++) {
        long long v = p[i];
        if (v < 0 || v >= NN) ok = 0;
    }
    g_is64 = ok;
}
// ---------------- zero (counts + pool) ----------------------------------------
__global__ void k_zero() {
    int i = blockIdx.x * blockDim.x + threadIdx.x;
    int stride = gridDim.x * blockDim.x;
    for (int j = i; j < NN; j += stride) g_CNT[j] = 0;
    for (int j = i; j < NG * CC; j += stride) g_gsum[j] = 0.f;
    for (int j = i; j < NG; j += stride) g_cnt[j] = 0.f;
}
// ---------------- edge convert + degree count ---------------------------------
__global__ void k_convert_edges(const void* ei) {
    int e = blockIdx.x * blockDim.x + threadIdx.x;
    if (e >= NEP) return;
    int s, d;
    if (e < NE) {
        if (g_is64) {
            const long long* p = (const long long*)ei;
            s = (int)p[e]; d = (int)p[NE + e];
        } else {
            const int* p = (const int*)ei;
            s = p[e]; d = p[NE + e];
        }
    } else {
        s = d = e - NE;   // self loop
    }
    g_SRC[e] = s;
    g_DST[e] = d;
    atomicAdd(&g_CNT[d], 1);
}
// ---------------- batch convert + per-graph node count ------------------------
__global__ void k_convert_batch(const void* bp) {
    int n = blockIdx.x * blockDim.x + threadIdx.x;
    if (n >= NN) return;
    int b = g_is64 ? (int)((const long long*)bp)[n] : ((const int*)bp)[n];
    g_BATCH[n] = b;
    atomicAdd(&g_cnt[b], 1.f);
}

// ---------------- CSR scan + scatter ------------------------------------------
__global__ __launch_bounds__(1024) void k_scan() {
    __shared__ int wsum[32];
    __shared__ int s_carry;
    int tid = threadIdx.x;
    int lane = tid & 31, warp = tid >> 5;
    if (tid == 0) s_carry = 0;
    __syncthreads();
    for (int base = 0; base < NN; base += 1024) {
        int v = (base + tid < NN) ? g_CNT[base + tid] : 0;
        int x = v;
#pragma unroll
        for (int o = 1; o < 32; o <<= 1) {
            int y = __shfl_up_sync(~0u, x, o);
            if (lane >= o) x += y;
        }
        if (lane == 31) wsum[warp] = x;
        __syncthreads();
        if (warp == 0) {
            int w = wsum[lane];
#pragma unroll
            for (int o = 1; o < 32; o <<= 1) {
                int y = __shfl_up_sync(~0u, w, o);
                if (lane >= o) w += y;
            }
            wsum[lane] = w;
        }
        __syncthreads();
        int warpoff = (warp == 0) ? 0 : wsum[warp - 1];
        int ex = s_carry + warpoff + x - v;
        if (base + tid < NN) { g_ROW[base + tid] = ex; g_WOFF[base + tid] = ex; }
        __syncthreads();
        if (tid == 1023) s_carry += warpoff + x;
        __syncthreads();
    }
    if (tid == 0) g_ROW[NN] = s_carry;
}
__global__ void k_scatter() {
    int e = blockIdx.x * blockDim.x + threadIdx.x;
    if (e >= NEP) return;
    int d = g_DST[e];
    int pos = atomicAdd(&g_WOFF[d], 1);
    g_CSRC[pos] = g_SRC[e];
}

// ---------------- h = X @ W -> g_A (+fp16 copy)  (8x4 register tile) ----------
__global__ __launch_bounds__(128) void k_gemm(const float* __restrict__ Xext,
                                              const float* __restrict__ W,
                                              int Din, int use_gb) {
    __shared__ float Wt[64 * 128];       // cols padded to 128
    __shared__ float Xs[64][GR + 4];
    const float* X = use_gb ? (const float*)g_B : Xext;
    int n0 = blockIdx.x * GR;
    int ct = threadIdx.x & 31;
    int rt = threadIdx.x >> 5;
    float acc[8][4];
#pragma unroll
    for (int i = 0; i < 8; i++)
#pragma unroll
        for (int j = 0; j < 4; j++) acc[i][j] = 0.f;

    for (int k0 = 0; k0 < Din; k0 += 64) {
        int kk = min(64, Din - k0);
        for (int idx = threadIdx.x; idx < kk * 128; idx += 128) {
            int k = idx >> 7, c = idx & 127;
            Wt[idx] = (c < CC) ? W[(size_t)(k0 + k) * CC + c] : 0.f;
        }
        for (int idx = threadIdx.x; idx < GR * kk; idx += 128) {
            int r = idx / kk, k = idx - r * kk;
            int n = n0 + r;
            Xs[k][r] = (n < NN) ? X[(size_t)n * Din + k0 + k] : 0.f;
        }
        __syncthreads();
        for (int k = 0; k < kk; k++) {
            float4 w  = *(const float4*)&Wt[k * 128 + ct * 4];
            float4 xa = *(const float4*)&Xs[k][rt * 8];
            float4 xb = *(const float4*)&Xs[k][rt * 8 + 4];
            float xr[8] = {xa.x, xa.y, xa.z, xa.w, xb.x, xb.y, xb.z, xb.w};
            float wr[4] = {w.x, w.y, w.z, w.w};
#pragma unroll
            for (int i = 0; i < 8; i++)
#pragma unroll
                for (int j = 0; j < 4; j++) acc[i][j] += xr[i] * wr[j];
        }
        __syncthreads();
    }
    if (ct < 25) {
#pragma unroll
        for (int i = 0; i < 8; i++) {
            int n = n0 + rt * 8 + i;
            if (n < NN) {
                float4 v = make_float4(acc[i][0], acc[i][1], acc[i][2], acc[i][3]);
                *(float4*)&g_A[(size_t)n * CC + ct * 4] = v;
                __half2* hp = (__half2*)&g_Ah[(size_t)n * CC + ct * 4];
                hp[0] = __floats2half2_rn(v.x, v.y);
                hp[1] = __floats2half2_rn(v.z, v.w);
            }
        }
    }
}

// ---------------- per-node attention scores -----------------------------------
__global__ void k_scores(const float* __restrict__ asrc, const float* __restrict__ adst) {
    int idx = blockIdx.x * blockDim.x + threadIdx.x;
    if (idx >= NN * HEADS) return;
    int n = idx / HEADS, h = idx - n * HEADS;
    float s1 = 0.f, s2 = 0.f;
#pragma unroll
    for (int f = 0; f < HID; f++) {
        float v = g_A[n * CC + h * HID + f];
        s1 += v * asrc[h * HID + f];
        s2 += v * adst[h * HID + f];
    }
    g_Ssrc[idx] = s1;
    g_Sdst[idx] = s2;
}

// ---------------- softmax per (dst, head): single pass, no max-shift ----------
__global__ void k_softmax() {
    int idx = blockIdx.x * blockDim.x + threadIdx.x;
    if (idx >= NN * HEADS) return;
    int d = idx / HEADS, h = idx - d * HEADS;
    int row0 = g_ROW[d], row1 = g_ROW[d + 1];
    float sd = g_Sdst[idx];
    float den = 0.f;
    for (int i = row0; i < row1; i++) {
        int s = g_CSRC[i];
        float a = g_Ssrc[s * HEADS + h] + sd;
        a = (a >= 0.f) ? a : NSLOPE * a;
        float ex = __expf(a);
        g_EXC[i * HEADS + h] = ex;
        den += ex;
    }
    g_IDen[idx] = 1.f / den;
}

// ---------------- aggregation: block-per-dst fp16 gather + bias + relu --------
__global__ __launch_bounds__(128) void k_agg(const float* __restrict__ bias) {
    int d = blockIdx.x;
    int c = threadIdx.x;
    if (c >= CC) return;
    int row0 = g_ROW[d], row1 = g_ROW[d + 1];
    int hh = c / HID;
    float invd = g_IDen[d * HEADS + hh];
    float acc = 0.f;
    for (int i = row0; i < row1; i++) {
        int s = g_CSRC[i];
        float ex = g_EXC[i * HEADS + hh];
        acc += ex * __half2float(g_Ah[(size_t)s * CC + c]);
    }
    float v = acc * invd + bias[c];
    g_B[(size_t)d * CC + c] = (v > 0.f) ? v : 0.f;
}

// ---------------- pooling -----------------------------------------------------
__global__ __launch_bounds__(128) void k_pool() {
    int c = threadIdx.x;
    if (c >= CC) return;
    int n0 = blockIdx.x * 256;
    if (n0 >= NN) return;
    int nend = min(n0 + 256, NN);
    int cur = g_BATCH[n0];
    float acc = 0.f;
    for (int n = n0; n < nend; n++) {
        int g = g_BATCH[n];
        if (g != cur) { atomicAdd(&g_gsum[cur * CC + c], acc); acc = 0.f; cur = g; }
        acc += g_B[(size_t)n * CC + c];
    }
    atomicAdd(&g_gsum[cur * CC + c], acc);
}

// ---------------- final FC ----------------------------------------------------
__global__ void k_fc(const float* __restrict__ Wfc, const float* __restrict__ bfc,
                     float* __restrict__ out) {
    int idx = blockIdx.x * blockDim.x + threadIdx.x;
    if (idx >= NG * NOUT) return;
    int g = idx / NOUT, o = idx - g * NOUT;
    float inv = 1.f / fmaxf(g_cnt[g], 1.f);
    float s = 0.f;
#pragma unroll 4
    for (int c = 0; c < CC; c++) s += g_gsum[g * CC + c] * Wfc[c * NOUT + o];
    out[idx] = s * inv + bfc[o];
}

// ---------------- driver ------------------------------------------------------
extern "C" void kernel_launch(void* const* d_in, const int* in_sizes, int n_in,
                              void* d_out, int out_size) {
    const float* x     = (const float*)d_in[0];
    const void*  ei    = d_in[1];
    const void*  batch = d_in[2];
    const float* W[3]    = { (const float*)d_in[3],  (const float*)d_in[7],  (const float*)d_in[11] };
    const float* asrc[3] = { (const float*)d_in[4],  (const float*)d_in[8],  (const float*)d_in[12] };
    const float* adst[3] = { (const float*)d_in[5],  (const float*)d_in[9],  (const float*)d_in[13] };
    const float* bb[3]   = { (const float*)d_in[6],  (const float*)d_in[10], (const float*)d_in[14] };
    const float* Wfc = (const float*)d_in[15];
    const float* bfc = (const float*)d_in[16];
    float* out = (float*)d_out;

    const int TB = 256;
    int gNH = (NN * HEADS + TB - 1) / TB;
    int gE  = (NEP + TB - 1) / TB;
    int gN  = (NN + TB - 1) / TB;

    // graph prep (per call)
    k_detect<<<1, 1>>>(ei);
    k_zero<<<256, TB>>>();
    k_convert_edges<<<gE, TB>>>(ei);
    k_convert_batch<<<gN, TB>>>(batch);
    k_scan<<<1, 1024>>>();
    k_scatter<<<gE, TB>>>();

    for (int l = 0; l < 3; l++) {
        int Din = (l == 0) ? 128 : CC;
        k_gemm<<<(NN + GR - 1) / GR, 128>>>(x, W[l], Din, l > 0 ? 1 : 0);
        k_scores<<<gNH, TB>>>(asrc[l], adst[l]);
        k_softmax<<<gNH, TB>>>();
        k_agg<<<NN, 128>>>(bb[l]);
    }

    k_pool<<<(NN + 255) / 256, 128>>>();
    k_fc<<<(NG * NOUT + TB - 1) / TB, TB>>>(Wfc, bfc, out);
}

// round 9
// speedup vs baseline: 3.5352x; 1.1279x over previous
#include <cuda_runtime.h>
#include <cuda_fp16.h>
#include <cfloat>

#define NN   50000
#define NE   800000
#define NEP  850000      // edges + self loops
#define HEADS 10
#define HID   10
#define CC    100        // HEADS*HID
#define NG    256
#define NOUT  10
#define NSLOPE 0.2f
#define GR   32          // gemm rows per block
#define TILE 24          // agg edges per smem tile

// ---------------- scratch (static device globals; no allocations) -------------
__device__ __half g_Ah[NN * CC];       // h in fp16 (aggregation gather)
__device__ float  g_B[NN * CC];        // layer input / aggregation output
__device__ int    g_SRC[NEP];
__device__ int    g_DST[NEP];
__device__ int    g_CSRC[NEP];         // CSR: src per position (sorted by dst)
__device__ int    g_CNT[NN];
__device__ int    g_ROW[NN + 1];
__device__ int    g_WOFF[NN];
__device__ int    g_BATCH[NN];
__device__ float  g_Ssrc[NN * HEADS];
__device__ float  g_Sdst[NN * HEADS];
__device__ float  g_gsum[NG * CC];
__device__ float  g_cnt[NG];
__device__ int    g_is64;

// ---------------- dtype detect ------------------------------------------------
__global__ void k_detect(const void* ei) {
    const long long* p = (const long long*)ei;
    int ok = 1;
    for (int i = 0; i < 16; i++) {
        long long v = p[i];
        if (v < 0 || v >= NN) ok = 0;
    }
    g_is64 = ok;
}
// ---------------- zero (counts + pool sums) -----------------------------------
__global__ void k_zero() {
    int i = blockIdx.x * blockDim.x + threadIdx.x;
    int stride = gridDim.x * blockDim.x;
    for (int j = i; j < NN; j += stride) g_CNT[j] = 0;
    for (int j = i; j < NG * CC; j += stride) g_gsum[j] = 0.f;
}
// ---------------- edge convert + degree count ---------------------------------
__global__ void k_convert_edges(const void* ei) {
    int e = blockIdx.x * blockDim.x + threadIdx.x;
    if (e >= NEP) return;
    int s, d;
    if (e < NE) {
        if (g_is64) {
            const long long* p = (const long long*)ei;
            s = (int)p[e]; d = (int)p[NE + e];
        } else {
            const int* p = (const int*)ei;
            s = p[e]; d = p[NE + e];
        }
    } else {
        s = d = e - NE;   // self loop
    }
    g_SRC[e] = s;
    g_DST[e] = d;
    atomicAdd(&g_CNT[d], 1);
}
// ---------------- batch convert (no atomics) ----------------------------------
__global__ void k_convert_batch(const void* bp) {
    int n = blockIdx.x * blockDim.x + threadIdx.x;
    if (n >= NN) return;
    g_BATCH[n] = g_is64 ? (int)((const long long*)bp)[n] : ((const int*)bp)[n];
}
// ---------------- per-graph node counts via binary search (sorted batch) ------
__global__ void k_graphcnt() {
    int g = threadIdx.x;                 // 0..255
    int lo = 0, hi = NN;
    while (lo < hi) { int mid = (lo + hi) >> 1; if (g_BATCH[mid] < g) lo = mid + 1; else hi = mid; }
    int a = lo;
    lo = 0; hi = NN;
    while (lo < hi) { int mid = (lo + hi) >> 1; if (g_BATCH[mid] < g + 1) lo = mid + 1; else hi = mid; }
    g_cnt[g] = (float)(lo - a);
}

// ---------------- CSR scan + scatter ------------------------------------------
__global__ __launch_bounds__(1024) void k_scan() {
    __shared__ int wsum[32];
    __shared__ int s_carry;
    int tid = threadIdx.x;
    int lane = tid & 31, warp = tid >> 5;
    if (tid == 0) s_carry = 0;
    __syncthreads();
    for (int base = 0; base < NN; base += 1024) {
        int v = (base + tid < NN) ? g_CNT[base + tid] : 0;
        int x = v;
#pragma unroll
        for (int o = 1; o < 32; o <<= 1) {
            int y = __shfl_up_sync(~0u, x, o);
            if (lane >= o) x += y;
        }
        if (lane == 31) wsum[warp] = x;
        __syncthreads();
        if (warp == 0) {
            int w = wsum[lane];
#pragma unroll
            for (int o = 1; o < 32; o <<= 1) {
                int y = __shfl_up_sync(~0u, w, o);
                if (lane >= o) w += y;
            }
            wsum[lane] = w;
        }
        __syncthreads();
        int warpoff = (warp == 0) ? 0 : wsum[warp - 1];
        int ex = s_carry + warpoff + x - v;
        if (base + tid < NN) { g_ROW[base + tid] = ex; g_WOFF[base + tid] = ex; }
        __syncthreads();
        if (tid == 1023) s_carry += warpoff + x;
        __syncthreads();
    }
    if (tid == 0) g_ROW[NN] = s_carry;
}
__global__ void k_scatter() {
    int e = blockIdx.x * blockDim.x + threadIdx.x;
    if (e >= NEP) return;
    int d = g_DST[e];
    int pos = atomicAdd(&g_WOFF[d], 1);
    g_CSRC[pos] = g_SRC[e];
}

// ---------------- fused: h = X@W (fp16 out) + attention scores ----------------
__global__ __launch_bounds__(128) void k_gemm(const float* __restrict__ Xext,
                                              const float* __restrict__ W,
                                              const float* __restrict__ asrc,
                                              const float* __restrict__ adst,
                                              int Din, int use_gb) {
    __shared__ float Wt[64 * 128];       // 32KB; reused as output stage (needs 3200)
    __shared__ float Xs[64][GR + 4];
    const float* X = use_gb ? (const float*)g_B : Xext;
    int n0 = blockIdx.x * GR;
    int ct = threadIdx.x & 31;
    int rt = threadIdx.x >> 5;
    float acc[8][4];
#pragma unroll
    for (int i = 0; i < 8; i++)
#pragma unroll
        for (int j = 0; j < 4; j++) acc[i][j] = 0.f;

    for (int k0 = 0; k0 < Din; k0 += 64) {
        int kk = min(64, Din - k0);
        for (int idx = threadIdx.x; idx < kk * 128; idx += 128) {
            int k = idx >> 7, c = idx & 127;
            Wt[idx] = (c < CC) ? W[(size_t)(k0 + k) * CC + c] : 0.f;
        }
        for (int idx = threadIdx.x; idx < GR * kk; idx += 128) {
            int r = idx / kk, k = idx - r * kk;
            int n = n0 + r;
            Xs[k][r] = (n < NN) ? X[(size_t)n * Din + k0 + k] : 0.f;
        }
        __syncthreads();
        for (int k = 0; k < kk; k++) {
            float4 w  = *(const float4*)&Wt[k * 128 + ct * 4];
            float4 xa = *(const float4*)&Xs[k][rt * 8];
            float4 xb = *(const float4*)&Xs[k][rt * 8 + 4];
            float xr[8] = {xa.x, xa.y, xa.z, xa.w, xb.x, xb.y, xb.z, xb.w};
            float wr[4] = {w.x, w.y, w.z, w.w};
#pragma unroll
            for (int i = 0; i < 8; i++)
#pragma unroll
                for (int j = 0; j < 4; j++) acc[i][j] += xr[i] * wr[j];
        }
        __syncthreads();
    }
    // epilogue: fp16 store + smem stage
    float* stage = Wt;   // [GR][CC]
    if (ct < 25) {
#pragma unroll
        for (int i = 0; i < 8; i++) {
            int r = rt * 8 + i;
            int n = n0 + r;
            stage[r * CC + ct * 4 + 0] = acc[i][0];
            stage[r * CC + ct * 4 + 1] = acc[i][1];
            stage[r * CC + ct * 4 + 2] = acc[i][2];
            stage[r * CC + ct * 4 + 3] = acc[i][3];
            if (n < NN) {
                __half2* hp = (__half2*)&g_Ah[(size_t)n * CC + ct * 4];
                hp[0] = __floats2half2_rn(acc[i][0], acc[i][1]);
                hp[1] = __floats2half2_rn(acc[i][2], acc[i][3]);
            }
        }
    }
    __syncthreads();
    // scores: 32 rows x 10 heads = 320 tasks
    for (int idx = threadIdx.x; idx < GR * HEADS; idx += 128) {
        int r = idx / HEADS, h = idx - r * HEADS;
        int n = n0 + r;
        if (n < NN) {
            float s1 = 0.f, s2 = 0.f;
#pragma unroll
            for (int f = 0; f < HID; f++) {
                float v = stage[r * CC + h * HID + f];
                s1 += v * asrc[h * HID + f];
                s2 += v * adst[h * HID + f];
            }
            g_Ssrc[n * HEADS + h] = s1;
            g_Sdst[n * HEADS + h] = s2;
        }
    }
}

// ---------------- fused softmax + aggregation (block per dst) -----------------
// coef = exp(a)/den; den factored out: acc = sum(exp*h), out = acc/den.
__global__ __launch_bounds__(128) void k_agg(const float* __restrict__ bias) {
    int d = blockIdx.x;
    int t = threadIdx.x;
    __shared__ float exv[TILE * HEADS];
    __shared__ int   ssrc[TILE];
    __shared__ float den[HEADS];
    __shared__ float sdst[HEADS];
    int row0 = g_ROW[d], row1 = g_ROW[d + 1];
    if (t < HEADS) { den[t] = 0.f; sdst[t] = g_Sdst[d * HEADS + t]; }
    __syncthreads();
    float2 acc = make_float2(0.f, 0.f);
    int hh = t / 5;                      // head of cols 2t,2t+1 (t<50)
    for (int t0 = row0; t0 < row1; t0 += TILE) {
        int nt = min(TILE, row1 - t0);
        // phase A: compute exp(alpha) for (edge, head) pairs
        for (int idx = t; idx < nt * HEADS; idx += 128) {
            int j = idx / HEADS, h = idx - j * HEADS;
            int s = g_CSRC[t0 + j];
            if (h == 0) ssrc[j] = s;
            float a = g_Ssrc[s * HEADS + h] + sdst[h];
            a = (a >= 0.f) ? a : NSLOPE * a;
            float ex = __expf(a);
            exv[j * HEADS + h] = ex;
            atomicAdd(&den[h], ex);
        }
        __syncthreads();
        // phase B: weighted gather (half2 per thread, cols 2t,2t+1)
        if (t < 50) {
            for (int j = 0; j < nt; j++) {
                int s = ssrc[j];
                float ex = exv[j * HEADS + hh];
                __half2 hv = *(const __half2*)&g_Ah[(size_t)s * CC + 2 * t];
                float2 f = __half22float2(hv);
                acc.x += ex * f.x;
                acc.y += ex * f.y;
            }
        }
        __syncthreads();
    }
    if (t < 50) {
        float invd = 1.f / den[hh];
        float vx = acc.x * invd + bias[2 * t];
        float vy = acc.y * invd + bias[2 * t + 1];
        vx = vx > 0.f ? vx : 0.f;
        vy = vy > 0.f ? vy : 0.f;
        *(float2*)&g_B[(size_t)d * CC + 2 * t] = make_float2(vx, vy);
    }
}

// ---------------- pooling -----------------------------------------------------
__global__ __launch_bounds__(128) void k_pool() {
    int c = threadIdx.x;
    if (c >= CC) return;
    int n0 = blockIdx.x * 256;
    if (n0 >= NN) return;
    int nend = min(n0 + 256, NN);
    int cur = g_BATCH[n0];
    float acc = 0.f;
    for (int n = n0; n < nend; n++) {
        int g = g_BATCH[n];
        if (g != cur) { atomicAdd(&g_gsum[cur * CC + c], acc); acc = 0.f; cur = g; }
        acc += g_B[(size_t)n * CC + c];
    }
    atomicAdd(&g_gsum[cur * CC + c], acc);
}

// ---------------- final FC ----------------------------------------------------
__global__ void k_fc(const float* __restrict__ Wfc, const float* __restrict__ bfc,
                     float* __restrict__ out) {
    int idx = blockIdx.x * blockDim.x + threadIdx.x;
    if (idx >= NG * NOUT) return;
    int g = idx / NOUT, o = idx - g * NOUT;
    float inv = 1.f / fmaxf(g_cnt[g], 1.f);
    float s = 0.f;
#pragma unroll 4
    for (int c = 0; c < CC; c++) s += g_gsum[g * CC + c] * Wfc[c * NOUT + o];
    out[idx] = s * inv + bfc[o];
}

// ---------------- driver ------------------------------------------------------
extern "C" void kernel_launch(void* const* d_in, const int* in_sizes, int n_in,
                              void* d_out, int out_size) {
    const float* x     = (const float*)d_in[0];
    const void*  ei    = d_in[1];
    const void*  batch = d_in[2];
    const float* W[3]    = { (const float*)d_in[3],  (const float*)d_in[7],  (const float*)d_in[11] };
    const float* asrc[3] = { (const float*)d_in[4],  (const float*)d_in[8],  (const float*)d_in[12] };
    const float* adst[3] = { (const float*)d_in[5],  (const float*)d_in[9],  (const float*)d_in[13] };
    const float* bb[3]   = { (const float*)d_in[6],  (const float*)d_in[10], (const float*)d_in[14] };
    const float* Wfc = (const float*)d_in[15];
    const float* bfc = (const float*)d_in[16];
    float* out = (float*)d_out;

    const int TB = 256;
    int gE = (NEP + TB - 1) / TB;
    int gN = (NN + TB - 1) / TB;

    // graph prep (per call)
    k_detect<<<1, 1>>>(ei);
    k_zero<<<196, TB>>>();
    k_convert_edges<<<gE, TB>>>(ei);
    k_convert_batch<<<gN, TB>>>(batch);
    k_graphcnt<<<1, 256>>>();
    k_scan<<<1, 1024>>>();
    k_scatter<<<gE, TB>>>();

    for (int l = 0; l < 3; l++) {
        int Din = (l == 0) ? 128 : CC;
        k_gemm<<<(NN + GR - 1) / GR, 128>>>(x, W[l], asrc[l], adst[l], Din, l > 0 ? 1 : 0);
        k_agg<<<NN, 128>>>(bb[l]);
    }

    k_pool<<<(NN + 255) / 256, 128>>>();
    k_fc<<<(NG * NOUT + TB - 1) / TB, TB>>>(Wfc, bfc, out);
}

// round 10
// speedup vs baseline: 3.6886x; 1.0434x over previous
#include <cuda_runtime.h>
#include <cuda_fp16.h>
#include <cfloat>

#define NN   50000
#define NE   800000
#define NEP  850000      // edges + self loops
#define HEADS 10
#define HID   10
#define CC    100        // HEADS*HID
#define NG    256
#define NOUT  10
#define NSLOPE 0.2f
#define GR   32          // gemm rows per block
#define TILE 32          // agg edges per smem tile

// ---------------- scratch (static device globals; no allocations) -------------
__device__ __half g_Ah[NN * CC];       // h in fp16 (aggregation gather)
__device__ float  g_B[NN * CC];        // layer input / aggregation output
__device__ int    g_SRC[NEP];
__device__ int    g_DST[NEP];
__device__ int    g_CSRC[NEP];         // CSR: src per position (sorted by dst)
__device__ int    g_CNT[NN];
__device__ int    g_ROW[NN + 1];
__device__ int    g_WOFF[NN];
__device__ int    g_BATCH[NN];
__device__ float  g_Ssrc[NN * HEADS];
__device__ float  g_Sdst[NN * HEADS];
__device__ float  g_gsum[NG * CC];
__device__ float  g_cnt[NG];
__device__ int    g_is64;

// ---------------- dtype detect ------------------------------------------------
__global__ void k_detect(const void* ei) {
    const long long* p = (const long long*)ei;
    int ok = 1;
    for (int i = 0; i < 16; i++) {
        long long v = p[i];
        if (v < 0 || v >= NN) ok = 0;
    }
    g_is64 = ok;
}
// ---------------- zero (counts + pool sums) -----------------------------------
__global__ void k_zero() {
    int i = blockIdx.x * blockDim.x + threadIdx.x;
    int stride = gridDim.x * blockDim.x;
    for (int j = i; j < NN; j += stride) g_CNT[j] = 0;
    for (int j = i; j < NG * CC; j += stride) g_gsum[j] = 0.f;
}
// ---------------- edge convert + degree count ---------------------------------
__global__ void k_convert_edges(const void* ei) {
    int e = blockIdx.x * blockDim.x + threadIdx.x;
    if (e >= NEP) return;
    int s, d;
    if (e < NE) {
        if (g_is64) {
            const long long* p = (const long long*)ei;
            s = (int)p[e]; d = (int)p[NE + e];
        } else {
            const int* p = (const int*)ei;
            s = p[e]; d = p[NE + e];
        }
    } else {
        s = d = e - NE;   // self loop
    }
    g_SRC[e] = s;
    g_DST[e] = d;
    atomicAdd(&g_CNT[d], 1);
}
// ---------------- batch convert (no atomics) ----------------------------------
__global__ void k_convert_batch(const void* bp) {
    int n = blockIdx.x * blockDim.x + threadIdx.x;
    if (n >= NN) return;
    g_BATCH[n] = g_is64 ? (int)((const long long*)bp)[n] : ((const int*)bp)[n];
}
// ---------------- per-graph node counts via binary search (sorted batch) ------
__global__ void k_graphcnt() {
    int g = threadIdx.x;                 // 0..255
    int lo = 0, hi = NN;
    while (lo < hi) { int mid = (lo + hi) >> 1; if (g_BATCH[mid] < g) lo = mid + 1; else hi = mid; }
    int a = lo;
    lo = 0; hi = NN;
    while (lo < hi) { int mid = (lo + hi) >> 1; if (g_BATCH[mid] < g + 1) lo = mid + 1; else hi = mid; }
    g_cnt[g] = (float)(lo - a);
}

// ---------------- CSR scan + scatter ------------------------------------------
__global__ __launch_bounds__(1024) void k_scan() {
    __shared__ int wsum[32];
    __shared__ int s_carry;
    int tid = threadIdx.x;
    int lane = tid & 31, warp = tid >> 5;
    if (tid == 0) s_carry = 0;
    __syncthreads();
    for (int base = 0; base < NN; base += 1024) {
        int v = (base + tid < NN) ? g_CNT[base + tid] : 0;
        int x = v;
#pragma unroll
        for (int o = 1; o < 32; o <<= 1) {
            int y = __shfl_up_sync(~0u, x, o);
            if (lane >= o) x += y;
        }
        if (lane == 31) wsum[warp] = x;
        __syncthreads();
        if (warp == 0) {
            int w = wsum[lane];
#pragma unroll
            for (int o = 1; o < 32; o <<= 1) {
                int y = __shfl_up_sync(~0u, w, o);
                if (lane >= o) w += y;
            }
            wsum[lane] = w;
        }
        __syncthreads();
        int warpoff = (warp == 0) ? 0 : wsum[warp - 1];
        int ex = s_carry + warpoff + x - v;
        if (base + tid < NN) { g_ROW[base + tid] = ex; g_WOFF[base + tid] = ex; }
        __syncthreads();
        if (tid == 1023) s_carry += warpoff + x;
        __syncthreads();
    }
    if (tid == 0) g_ROW[NN] = s_carry;
}
__global__ void k_scatter() {
    int e = blockIdx.x * blockDim.x + threadIdx.x;
    if (e >= NEP) return;
    int d = g_DST[e];
    int pos = atomicAdd(&g_WOFF[d], 1);
    g_CSRC[pos] = g_SRC[e];
}

// ---------------- fused: h = X@W (fp16 out) + attention scores ----------------
__global__ __launch_bounds__(128) void k_gemm(const float* __restrict__ Xext,
                                              const float* __restrict__ W,
                                              const float* __restrict__ asrc,
                                              const float* __restrict__ adst,
                                              int Din, int use_gb) {
    __shared__ float Wt[64 * 128];       // 32KB; reused as output stage (needs 3200)
    __shared__ float Xs[64][GR + 4];
    const float* X = use_gb ? (const float*)g_B : Xext;
    int n0 = blockIdx.x * GR;
    int ct = threadIdx.x & 31;
    int rt = threadIdx.x >> 5;
    float acc[8][4];
#pragma unroll
    for (int i = 0; i < 8; i++)
#pragma unroll
        for (int j = 0; j < 4; j++) acc[i][j] = 0.f;

    for (int k0 = 0; k0 < Din; k0 += 64) {
        int kk = min(64, Din - k0);
        for (int idx = threadIdx.x; idx < kk * 128; idx += 128) {
            int k = idx >> 7, c = idx & 127;
            Wt[idx] = (c < CC) ? W[(size_t)(k0 + k) * CC + c] : 0.f;
        }
        for (int idx = threadIdx.x; idx < GR * kk; idx += 128) {
            int r = idx / kk, k = idx - r * kk;
            int n = n0 + r;
            Xs[k][r] = (n < NN) ? X[(size_t)n * Din + k0 + k] : 0.f;
        }
        __syncthreads();
        for (int k = 0; k < kk; k++) {
            float4 w  = *(const float4*)&Wt[k * 128 + ct * 4];
            float4 xa = *(const float4*)&Xs[k][rt * 8];
            float4 xb = *(const float4*)&Xs[k][rt * 8 + 4];
            float xr[8] = {xa.x, xa.y, xa.z, xa.w, xb.x, xb.y, xb.z, xb.w};
            float wr[4] = {w.x, w.y, w.z, w.w};
#pragma unroll
            for (int i = 0; i < 8; i++)
#pragma unroll
                for (int j = 0; j < 4; j++) acc[i][j] += xr[i] * wr[j];
        }
        __syncthreads();
    }
    // epilogue: fp16 store + smem stage
    float* stage = Wt;   // [GR][CC]
    if (ct < 25) {
#pragma unroll
        for (int i = 0; i < 8; i++) {
            int r = rt * 8 + i;
            int n = n0 + r;
            stage[r * CC + ct * 4 + 0] = acc[i][0];
            stage[r * CC + ct * 4 + 1] = acc[i][1];
            stage[r * CC + ct * 4 + 2] = acc[i][2];
            stage[r * CC + ct * 4 + 3] = acc[i][3];
            if (n < NN) {
                __half2* hp = (__half2*)&g_Ah[(size_t)n * CC + ct * 4];
                hp[0] = __floats2half2_rn(acc[i][0], acc[i][1]);
                hp[1] = __floats2half2_rn(acc[i][2], acc[i][3]);
            }
        }
    }
    __syncthreads();
    // scores: 32 rows x 10 heads = 320 tasks
    for (int idx = threadIdx.x; idx < GR * HEADS; idx += 128) {
        int r = idx / HEADS, h = idx - r * HEADS;
        int n = n0 + r;
        if (n < NN) {
            float s1 = 0.f, s2 = 0.f;
#pragma unroll
            for (int f = 0; f < HID; f++) {
                float v = stage[r * CC + h * HID + f];
                s1 += v * asrc[h * HID + f];
                s2 += v * adst[h * HID + f];
            }
            g_Ssrc[n * HEADS + h] = s1;
            g_Sdst[n * HEADS + h] = s2;
        }
    }
}

// ---------------- fused softmax + aggregation (block per dst) -----------------
// out = (sum_i exp(a_i) h_i) / (sum_i exp(a_i)); den accumulated in phase B regs.
// threads 0..49: even edges; threads 64..113: odd edges; smem reduce at end.
__global__ __launch_bounds__(128) void k_agg(const float* __restrict__ bias) {
    int d = blockIdx.x;
    int t = threadIdx.x;
    __shared__ float exv[TILE * HEADS];
    __shared__ int   ssrc[TILE];
    __shared__ float sdst[HEADS];
    __shared__ float red[3 * 50];       // partials from the odd-edge group
    int row0 = g_ROW[d], row1 = g_ROW[d + 1];
    if (t < HEADS) sdst[t] = g_Sdst[d * HEADS + t];
    __syncthreads();
    bool lo = (t < 50);
    bool hi = (t >= 64 && t < 114);
    int cp = lo ? t : (t - 64);          // col pair id 0..49
    int hh = cp / 5;                     // head of cols 2cp, 2cp+1
    float ax = 0.f, ay = 0.f, dn = 0.f;
    for (int t0 = row0; t0 < row1; t0 += TILE) {
        int nt = min(TILE, row1 - t0);
        // phase A: exp(alpha) for (edge, head)
        for (int idx = t; idx < nt * HEADS; idx += 128) {
            int j = idx / HEADS, h = idx - j * HEADS;
            int s = g_CSRC[t0 + j];
            if (h == 0) ssrc[j] = s;
            float a = g_Ssrc[s * HEADS + h] + sdst[h];
            a = (a >= 0.f) ? a : NSLOPE * a;
            exv[j * HEADS + h] = __expf(a);
        }
        __syncthreads();
        // phase B: weighted gather, 2-way edge-parallel
        if (lo || hi) {
            for (int j = lo ? 0 : 1; j < nt; j += 2) {
                int s = ssrc[j];
                float ex = exv[j * HEADS + hh];
                __half2 hv = *(const __half2*)&g_Ah[(size_t)s * CC + 2 * cp];
                float2 f = __half22float2(hv);
                ax += ex * f.x;
                ay += ex * f.y;
                dn += ex;
            }
        }
        __syncthreads();
    }
    if (hi) { red[cp] = ax; red[50 + cp] = ay; red[100 + cp] = dn; }
    __syncthreads();
    if (lo) {
        ax += red[cp];
        ay += red[50 + cp];
        dn += red[100 + cp];
        float invd = 1.f / dn;
        float vx = ax * invd + bias[2 * cp];
        float vy = ay * invd + bias[2 * cp + 1];
        vx = vx > 0.f ? vx : 0.f;
        vy = vy > 0.f ? vy : 0.f;
        *(float2*)&g_B[(size_t)d * CC + 2 * cp] = make_float2(vx, vy);
    }
}

// ---------------- pooling -----------------------------------------------------
__global__ __launch_bounds__(128) void k_pool() {
    int c = threadIdx.x;
    if (c >= CC) return;
    int n0 = blockIdx.x * 256;
    if (n0 >= NN) return;
    int nend = min(n0 + 256, NN);
    int cur = g_BATCH[n0];
    float acc = 0.f;
    for (int n = n0; n < nend; n++) {
        int g = g_BATCH[n];
        if (g != cur) { atomicAdd(&g_gsum[cur * CC + c], acc); acc = 0.f; cur = g; }
        acc += g_B[(size_t)n * CC + c];
    }
    atomicAdd(&g_gsum[cur * CC + c], acc);
}

// ---------------- final FC ----------------------------------------------------
__global__ void k_fc(const float* __restrict__ Wfc, const float* __restrict__ bfc,
                     float* __restrict__ out) {
    int idx = blockIdx.x * blockDim.x + threadIdx.x;
    if (idx >= NG * NOUT) return;
    int g = idx / NOUT, o = idx - g * NOUT;
    float inv = 1.f / fmaxf(g_cnt[g], 1.f);
    float s = 0.f;
#pragma unroll 4
    for (int c = 0; c < CC; c++) s += g_gsum[g * CC + c] * Wfc[c * NOUT + o];
    out[idx] = s * inv + bfc[o];
}

// ---------------- driver ------------------------------------------------------
extern "C" void kernel_launch(void* const* d_in, const int* in_sizes, int n_in,
                              void* d_out, int out_size) {
    const float* x     = (const float*)d_in[0];
    const void*  ei    = d_in[1];
    const void*  batch = d_in[2];
    const float* W[3]    = { (const float*)d_in[3],  (const float*)d_in[7],  (const float*)d_in[11] };
    const float* asrc[3] = { (const float*)d_in[4],  (const float*)d_in[8],  (const float*)d_in[12] };
    const float* adst[3] = { (const float*)d_in[5],  (const float*)d_in[9],  (const float*)d_in[13] };
    const float* bb[3]   = { (const float*)d_in[6],  (const float*)d_in[10], (const float*)d_in[14] };
    const float* Wfc = (const float*)d_in[15];
    const float* bfc = (const float*)d_in[16];
    float* out = (float*)d_out;

    const int TB = 256;
    int gE = (NEP + TB - 1) / TB;
    int gN = (NN + TB - 1) / TB;

    // graph prep (per call)
    k_detect<<<1, 1>>>(ei);
    k_zero<<<196, TB>>>();
    k_convert_edges<<<gE, TB>>>(ei);
    k_convert_batch<<<gN, TB>>>(batch);
    k_graphcnt<<<1, 256>>>();
    k_scan<<<1, 1024>>>();
    k_scatter<<<gE, TB>>>();

    for (int l = 0; l < 3; l++) {
        int Din = (l == 0) ? 128 : CC;
        k_gemm<<<(NN + GR - 1) / GR, 128>>>(x, W[l], asrc[l], adst[l], Din, l > 0 ? 1 : 0);
        k_agg<<<NN, 128>>>(bb[l]);
    }

    k_pool<<<(NN + 255) / 256, 128>>>();
    k_fc<<<(NG * NOUT + TB - 1) / TB, TB>>>(Wfc, bfc, out);
}